// round 17
// baseline (speedup 1.0000x reference)
#include <cuda_runtime.h>

#define VOCAB_ 32000
#define B_ 1000
#define T_ 512
#define L_ 25
#define E_ 64
#define H_ 8
#define TICKS (T_ + L_ - 1)        // 536
#define SCALE 2.8853900817779268f  // 2*log2(e), folded into weights

// vproj[v][j] = 2^( SCALE*(emb[v]@W_xh0[:,j] + b_h[0][j] + sum_k W_hh[0][k][j]) )
__device__ float g_vproj[(size_t)VOCAB_ * H_];

typedef unsigned long long ull;

__device__ __forceinline__ void fma2(ull& d, ull a, ull b) {
    asm("fma.rn.f32x2 %0, %1, %2, %0;" : "+l"(d) : "l"(a), "l"(b));
}
__device__ __forceinline__ ull mul2(ull a, ull b) {           // d = a*b (fresh dst)
    ull d; asm("mul.rn.f32x2 %0, %1, %2;" : "=l"(d) : "l"(a), "l"(b));
    return d;
}
__device__ __forceinline__ ull pk(float lo, float hi) {
    ull r; asm("mov.b64 %0, {%1, %2};" : "=l"(r) : "f"(lo), "f"(hi)); return r;
}
__device__ __forceinline__ float2 upk(ull p) {
    float2 r; asm("mov.b64 {%0, %1}, %2;" : "=f"(r.x), "=f"(r.y) : "l"(p)); return r;
}
__device__ __forceinline__ float ex2f(float y) {
    float e; asm("ex2.approx.f32 %0, %1;" : "=f"(e) : "f"(y)); return e;
}
__device__ __forceinline__ float rcpf(float d) {
    float r; asm("rcp.approx.f32 %0, %1;" : "=f"(r) : "f"(d)); return r;
}

// -------- Kernel 1: vproj = 2^(scaled xproj + layer-0 bias + Whh fold) --------
__global__ void vproj_kernel(const float* __restrict__ emb,
                             const float* __restrict__ W_xh0,
                             const float* __restrict__ b_h,
                             const float* __restrict__ W_hh) {
    __shared__ float sW[E_ * H_];
    __shared__ float sb[H_];    // b_h[0][j] + sum_k W_hh[0][k][j]
    for (int i = threadIdx.x; i < E_ * H_; i += blockDim.x) sW[i] = W_xh0[i];
    if (threadIdx.x < H_) {
        int j = threadIdx.x;
        float c = b_h[j];
#pragma unroll
        for (int k = 0; k < H_; k++) c += W_hh[k * H_ + j];   // layer 0 rows
        sb[j] = c;
    }
    __syncthreads();

    int v = blockIdx.x * blockDim.x + threadIdx.x;
    if (v >= VOCAB_) return;

    const float4* e4 = (const float4*)(emb + (long)v * E_);
    float acc[H_];
#pragma unroll
    for (int j = 0; j < H_; j++) acc[j] = sb[j];
#pragma unroll
    for (int k4 = 0; k4 < E_ / 4; k4++) {
        float4 ev = e4[k4];
#pragma unroll
        for (int j = 0; j < H_; j++) {
            acc[j] += ev.x * sW[(k4 * 4 + 0) * H_ + j];
            acc[j] += ev.y * sW[(k4 * 4 + 1) * H_ + j];
            acc[j] += ev.z * sW[(k4 * 4 + 2) * H_ + j];
            acc[j] += ev.w * sW[(k4 * 4 + 3) * H_ + j];
        }
    }
    float4* dst = (float4*)(g_vproj + (long)v * H_);
    dst[0] = make_float4(ex2f(acc[0] * SCALE), ex2f(acc[1] * SCALE),
                         ex2f(acc[2] * SCALE), ex2f(acc[3] * SCALE));
    dst[1] = make_float4(ex2f(acc[4] * SCALE), ex2f(acc[5] * SCALE),
                         ex2f(acc[6] * SCALE), ex2f(acc[7] * SCALE));
}

// ---- one wavefront tick (r-state, C-form). C row passed in registers,
// prefetched one tick ahead by the caller. r = 1/(2^y * C + 1).
template<bool GUARD>
__device__ __forceinline__ void tick(
    ull hp[4], const ull wx2[32], const ull whh2[32],
    float4 c0, float4 c1, bool valid) {

    ull vp0 = __shfl_up_sync(0xffffffffu, hp[0], 1);
    ull vp1 = __shfl_up_sync(0xffffffffu, hp[1], 1);
    ull vp2 = __shfl_up_sync(0xffffffffu, hp[2], 1);
    ull vp3 = __shfl_up_sync(0xffffffffu, hp[3], 1);

    ull ac[8];
#pragma unroll
    for (int j = 0; j < 8; j++) {
        ull a = mul2(hp[0], whh2[j * 4 + 0]);
        fma2(a, hp[1], whh2[j * 4 + 1]);
        fma2(a, hp[2], whh2[j * 4 + 2]);
        fma2(a, hp[3], whh2[j * 4 + 3]);
        fma2(a, vp0, wx2[j * 4 + 0]);
        fma2(a, vp1, wx2[j * 4 + 1]);
        fma2(a, vp2, wx2[j * 4 + 2]);
        fma2(a, vp3, wx2[j * 4 + 3]);
        ac[j] = a;
    }
    const float C[8] = {c0.x, c0.y, c0.z, c0.w, c1.x, c1.y, c1.z, c1.w};
    float n[8];
#pragma unroll
    for (int j = 0; j < 8; j++) {
        float2 u = upk(ac[j]);
        float e = ex2f(u.x + u.y);
        n[j] = rcpf(fmaf(e, C[j], 1.0f));
    }
    if (GUARD) {
        if (valid) {
#pragma unroll
            for (int p = 0; p < 4; p++) hp[p] = pk(n[2 * p], n[2 * p + 1]);
        }
    } else {
#pragma unroll
        for (int p = 0; p < 4; p++) hp[p] = pk(n[2 * p], n[2 * p + 1]);
    }
}

// -------- Kernel 2: warp-per-element wavefront, prefetched C stream --------
__global__ void __launch_bounds__(256, 1) rnn_pf_kernel(
    const int*   __restrict__ x,           // [B, T]
    const float* __restrict__ h0,          // [L, B, H]
    const float* __restrict__ W_xh_rest,   // [L-1, H, H]
    const float* __restrict__ W_hh,        // [L, H, H]
    const float* __restrict__ b_h,         // [L, H]
    const float* __restrict__ W_hy,        // [H, 1]
    const float* __restrict__ b_y,         // [1]
    float* __restrict__ out, int out_size) {

    extern __shared__ float smem[];
    float* sbias = smem;                   // [32][8] static exp-biases C (1 KB)
    float* sx    = smem + 32 * H_;         // [8 elems][T][8] C0 rows (128 KB)

    const int lane = threadIdx.x & 31;
    const int warp = threadIdx.x >> 5;     // 0..7, one elem per warp
    const int b    = blockIdx.x * 8 + warp;
    const bool act   = (lane < L_);
    const bool hasWx = (lane >= 1) && act;
    const bool lane0 = (lane == 0);

    // ---- stage exp'd x-projection rows for this block's 8 elements ----
    {
        const ulonglong2* vp = (const ulonglong2*)g_vproj;
        ulonglong2* dst = (ulonglong2*)sx;
        for (int q = threadIdx.x; q < 8 * T_; q += 256) {
            int e = q >> 9;
            int t = q & (T_ - 1);
            int id = x[(long)(blockIdx.x * 8 + e) * T_ + t];
            dst[q * 2 + 0] = vp[(long)id * 2 + 0];
            dst[q * 2 + 1] = vp[(long)id * 2 + 1];
        }
    }

    // ---- weights, r-state transformed: W' = -2*SCALE*W; C = 2^(folded bias) ----
    ull wx2[32], whh2[32];
    float bsum[8];
#pragma unroll
    for (int j = 0; j < 8; j++) {
        float bs = 0.0f;   // SCALE * (b_j + sum_k Wx[k,j] + sum_k Whh[k,j])
#pragma unroll
        for (int p = 0; p < 4; p++) {
            float a = 0.f, c = 0.f;
            if (hasWx) {
                float w0 = W_xh_rest[((lane - 1) * H_ + 2 * p) * H_ + j];
                float w1 = W_xh_rest[((lane - 1) * H_ + 2 * p + 1) * H_ + j];
                a = -2.0f * SCALE * w0;
                c = -2.0f * SCALE * w1;
                bs += SCALE * (w0 + w1);
            }
            wx2[j * 4 + p] = pk(a, c);
            float d = 0.f, f = 0.f;
            if (act) {
                float w0 = W_hh[(lane * H_ + 2 * p) * H_ + j];
                float w1 = W_hh[(lane * H_ + 2 * p + 1) * H_ + j];
                d = -2.0f * SCALE * w0;
                f = -2.0f * SCALE * w1;
                bs += SCALE * (w0 + w1);
            }
            whh2[j * 4 + p] = pk(d, f);
        }
        if (hasWx) bs += SCALE * b_h[lane * H_ + j];
        bsum[j] = bs;
    }
    if (warp == 0) {
#pragma unroll
        for (int j = 0; j < 8; j++) sbias[lane * H_ + j] = ex2f(bsum[j]);
    }

    // ---- hidden state as r-form: r = (1 - h)/2 ----
    ull hp[4];
#pragma unroll
    for (int p = 0; p < 4; p++) {
        float a0 = act ? h0[(lane * B_ + b) * H_ + 2 * p]     : 0.f;
        float a1 = act ? h0[(lane * B_ + b) * H_ + 2 * p + 1] : 0.f;
        hp[p] = pk(0.5f * (1.0f - a0), 0.5f * (1.0f - a1));
    }

    __syncthreads();

    // per-lane C pointer: lane0 walks its C0 stream, others static exp-bias
    const float* cptr = lane0 ? (sx + (long)warp * T_ * H_) : (sbias + lane * H_);
    const int binc = lane0 ? H_ : 0;

    // prefetch C row for tick 0
    float4 c0 = ((const float4*)cptr)[0];
    float4 c1 = ((const float4*)cptr)[1];
    cptr += binc;

    int s = 0;
    // ---- ramp-up: guarded commits ----
#pragma unroll 1
    for (; s < L_ - 1; s++) {
        float4 p0 = ((const float4*)cptr)[0];       // prefetch tick s+1
        float4 p1 = ((const float4*)cptr)[1];
        cptr += binc;
        tick<true>(hp, wx2, whh2, c0, c1, s >= lane);
        c0 = p0; c1 = p1;
    }
    // ---- steady: unconditional commits, C prefetched a tick ahead ----
#pragma unroll 4
    for (; s < T_ - 1; s++) {
        float4 p0 = ((const float4*)cptr)[0];       // prefetch tick s+1
        float4 p1 = ((const float4*)cptr)[1];
        cptr += binc;
        tick<false>(hp, wx2, whh2, c0, c1, true);
        c0 = p0; c1 = p1;
    }
    tick<false>(hp, wx2, whh2, c0, c1, true);       // s = T-1 (last consume)
    s++;
    // ---- ramp-down: guarded (freeze finished lanes); C values unused ----
#pragma unroll 1
    for (; s < TICKS; s++) {
        tick<true>(hp, wx2, whh2, c0, c1, lane >= s - (T_ - 1));
    }

    // ---- outputs: convert h = 1 - 2r ----
    if (act && out_size >= B_ + L_ * B_ * H_) {
#pragma unroll
        for (int p = 0; p < 4; p++) {
            float2 u = upk(hp[p]);
            out[B_ + (lane * B_ + b) * H_ + 2 * p]     = fmaf(u.x, -2.0f, 1.0f);
            out[B_ + (lane * B_ + b) * H_ + 2 * p + 1] = fmaf(u.y, -2.0f, 1.0f);
        }
    }
    if (lane == L_ - 1) {
        float sv = b_y[0];
#pragma unroll
        for (int p = 0; p < 4; p++) {
            float2 u = upk(hp[p]);
            sv += fmaf(u.x, -2.0f, 1.0f) * W_hy[2 * p]
                + fmaf(u.y, -2.0f, 1.0f) * W_hy[2 * p + 1];
        }
        if (b < out_size) out[b] = sv;
    }
}

extern "C" void kernel_launch(void* const* d_in, const int* in_sizes, int n_in,
                              void* d_out, int out_size) {
    const int*   x          = (const int*)d_in[0];
    const float* h0         = (const float*)d_in[1];
    const float* emb        = (const float*)d_in[2];
    const float* W_xh0      = (const float*)d_in[3];
    const float* W_xh_rest  = (const float*)d_in[4];
    const float* W_hh       = (const float*)d_in[5];
    const float* b_h        = (const float*)d_in[6];
    const float* W_hy       = (const float*)d_in[7];
    const float* b_y        = (const float*)d_in[8];

    vproj_kernel<<<(VOCAB_ + 255) / 256, 256>>>(emb, W_xh0, b_h, W_hh);

    const int smem_bytes = (32 * H_ + 8 * T_ * H_) * 4;   // 1 KB + 128 KB
    cudaFuncSetAttribute(rnn_pf_kernel,
                         cudaFuncAttributeMaxDynamicSharedMemorySize, smem_bytes);
    rnn_pf_kernel<<<B_ / 8, 256, smem_bytes>>>(x, h0, W_xh_rest, W_hh, b_h,
                                               W_hy, b_y, (float*)d_out, out_size);
}